// round 9
// baseline (speedup 1.0000x reference)
#include <cuda_runtime.h>
#include <cstdint>

typedef unsigned long long ull;

// dims
constexpr int Bn = 16, Nn = 2000, En = 3000, Cn = 17, Wn_ = 12, Dn = 16, On = 256, Kk = 3, NBn = 3;
constexpr int BC = Bn * Cn;   // 272
constexpr int BCp = 288;      // padded column count for diffusion GEMMs
constexpr int KC = Kk * Cn;   // 51
constexpr int O4 = On / 4, O8 = On / 8, O2 = On / 2;
constexpr int SPL = 6;        // split-K planes (diffusion, hodge)
constexpr int SPLI = 10;      // split-K planes (incidence)

#define NEG_HUGE -1e30f

// ---------------- scratch (static device globals; no allocs) ----------------
__device__ float g_neT[Dn * Nn];
__device__ float g_S[(size_t)Nn * Nn];          // 16 MB
__device__ float g_r[Nn];                        // reciprocal row sums
__device__ float g_W[(size_t)Nn * KC * O4];     // 26 MB adaptive weights
__device__ float g_wwt[Nn * O2];
__device__ float g_wws[Nn * O8];
__device__ float g_bias[Nn * On];
__device__ float g_X0[Nn * BCp];
__device__ float g_Y1[Nn * BCp];
__device__ float g_Y2[Nn * BCp];
__device__ float g_pp[(size_t)SPL * Nn * BCp];  // split-K partials (diffusion)
__device__ float g_XEu[Bn * En];
__device__ float g_XEv[Bn * En];
__device__ float g_hpart[SPL * Bn * En];
__device__ float g_XEST[En * Bn];
__device__ float g_ipart[SPLI * Nn * Bn];
__device__ float g_Mm[Bn * Nn];
__device__ float g_G[Nn];
__device__ float g_ts[Bn * Nn];

// ---------------- helpers ----------------
__device__ __forceinline__ void fma2(ull& acc, ull a, ull b) {
    asm("fma.rn.f32x2 %0, %1, %2, %0;" : "+l"(acc) : "l"(a), "l"(b));
}
__device__ __forceinline__ ull pack2(float lo, float hi) {
    ull r;
    asm("mov.b64 %0, {%1,%2};" : "=l"(r) : "f"(lo), "f"(hi));
    return r;
}
__device__ __forceinline__ void unpack2(float& lo, float& hi, ull v) {
    asm("mov.b64 {%0,%1}, %2;" : "=f"(lo), "=f"(hi) : "l"(v));
}
__device__ __forceinline__ float f2tf(float f) {
    uint32_t r;
    asm("cvt.rna.tf32.f32 %0, %1;" : "=r"(r) : "f"(f));
    return __uint_as_float(r);
}
__device__ __forceinline__ void mma_tf32(float* d, const uint32_t* a, const uint32_t* b) {
    asm("mma.sync.aligned.m16n8k8.row.col.f32.tf32.tf32.f32 "
        "{%0,%1,%2,%3}, {%4,%5,%6,%7}, {%8,%9}, {%0,%1,%2,%3};"
        : "+f"(d[0]), "+f"(d[1]), "+f"(d[2]), "+f"(d[3])
        : "r"(a[0]), "r"(a[1]), "r"(a[2]), "r"(a[3]), "r"(b[0]), "r"(b[1]));
}

__device__ __forceinline__ float blk_reduce(float v, float* red, bool do_max) {
    int tid = threadIdx.x;
    red[tid] = v;
    __syncthreads();
#pragma unroll
    for (int s = 128; s > 0; s >>= 1) {
        if (tid < s) red[tid] = do_max ? fmaxf(red[tid], red[tid + s]) : (red[tid] + red[tid + s]);
        __syncthreads();
    }
    float r = red[0];
    __syncthreads();
    return r;
}

// ---------------- kernels ----------------

__global__ void k_transpose_ne(const float* __restrict__ ne) {
    int idx = blockIdx.x * 256 + threadIdx.x;
    if (idx < Nn * Dn) {
        int n = idx >> 4, d = idx & 15;
        g_neT[d * Nn + n] = ne[idx];
    }
}

// Fused S-branch: recompute relu(ne@neT)+diag into smem, softmax (or adj*exp),
// single global write of S + reciprocal rowsums. 8 rows/block, warp-per-row.
__global__ void k_S_fused(const float* __restrict__ ne, const float* __restrict__ adj,
                          const int* __restrict__ fa_ptr, const int* __restrict__ stay_ptr) {
    extern __shared__ float s0s[];  // 8 * Nn floats (64 KB)
    __shared__ float neS[8 * 16];
    int tid = threadIdx.x;
    int r0 = blockIdx.x * 8;
    if (tid < 128) neS[tid] = ne[r0 * 16 + tid];
    __syncthreads();
    float stayv = (float)stay_ptr[0];
    for (int j = tid; j < Nn; j += 256) {
        float nt[16];
#pragma unroll
        for (int d = 0; d < 16; d++) nt[d] = g_neT[d * Nn + j];
#pragma unroll
        for (int r = 0; r < 8; r++) {
            float s = 0.f;
#pragma unroll
            for (int d = 0; d < 16; d++) s += neS[r * 16 + d] * nt[d];
            s = fmaxf(s, 0.f);
            if (r0 + r == j) s = stayv;
            s0s[r * Nn + j] = s;
        }
    }
    __syncthreads();
    int w = tid >> 5, lane = tid & 31;
    int row = r0 + w;
    float* srow_s = s0s + w * Nn;
    float* srow_g = g_S + (size_t)row * Nn;
    if (fa_ptr[0] == 0) {
        float m = NEG_HUGE;
        for (int j = lane; j < Nn; j += 32) m = fmaxf(m, srow_s[j]);
#pragma unroll
        for (int o = 16; o; o >>= 1) m = fmaxf(m, __shfl_xor_sync(0xffffffffu, m, o));
        float z = 0.f;
        for (int j = lane; j < Nn; j += 32) {
            float e = expf(srow_s[j] - m);
            srow_s[j] = e;
            z += e;
        }
#pragma unroll
        for (int o = 16; o; o >>= 1) z += __shfl_xor_sync(0xffffffffu, z, o);
        float inv = 1.f / z;
        float s2 = 0.f;
        for (int j = lane; j < Nn; j += 32) {
            float v = srow_s[j] * inv;
            srow_g[j] = v;
            s2 += v;
        }
#pragma unroll
        for (int o = 16; o; o >>= 1) s2 += __shfl_xor_sync(0xffffffffu, s2, o);
        if (lane == 0) g_r[row] = 1.f / s2;
    } else {
        float s2 = 0.f;
        for (int j = lane; j < Nn; j += 32) {
            float v = adj[(size_t)row * Nn + j] * expf(srow_s[j]);
            srow_g[j] = v;
            s2 += v;
        }
#pragma unroll
        for (int o = 16; o; o >>= 1) s2 += __shfl_xor_sync(0xffffffffu, s2, o);
        if (lane == 0) g_r[row] = 1.f / s2;
    }
}

// Store-bound outer product: C[n,c] = sum_d ne[n,d] * B[d,c]. Ncols % 4 == 0.
// Block: 256-col x 125-row tile. Threads: 4 rowlanes x 64 col-float4s.
__global__ void k_outer16(const float* __restrict__ ne, const float* __restrict__ B,
                          float* __restrict__ C, int Ncols) {
    __shared__ float4 Bs[16][64];
    __shared__ float neS[125 * 16];
    int tid = threadIdx.x;
    int c0 = blockIdx.x * 256, r0 = blockIdx.y * 125;
    for (int i = tid; i < 16 * 64; i += 256) {
        int d = i >> 6, cg = i & 63;
        int c = c0 + cg * 4;
        float4 v = {0.f, 0.f, 0.f, 0.f};
        if (c < Ncols) v = *reinterpret_cast<const float4*>(B + (size_t)d * Ncols + c);
        Bs[d][cg] = v;
    }
    for (int i = tid; i < 125 * 16; i += 256) neS[i] = ne[r0 * 16 + i];
    __syncthreads();
    int tr = tid >> 6, tc = tid & 63;
    int c = c0 + tc * 4;
    if (c >= Ncols) return;
    for (int rr = tr; rr < 125; rr += 4) {
        float4 acc = {0.f, 0.f, 0.f, 0.f};
#pragma unroll
        for (int d = 0; d < 16; d++) {
            float a = neS[rr * 16 + d];
            float4 b = Bs[d][tc];
            acc.x += a * b.x;
            acc.y += a * b.y;
            acc.z += a * b.z;
            acc.w += a * b.w;
        }
        *reinterpret_cast<float4*>(C + (size_t)(r0 + rr) * Ncols + c) = acc;
    }
}

// ---------------- tf32 tensor-core GEMM (m16n8k8), double-buffered, split-K ----
template <int BM, int BN, int BK, int WCOL, int MI, int NI, int NT, int SCALE_A>
__global__ void __launch_bounds__(NT) k_tfgemm(
        const float* __restrict__ A, const float* __restrict__ B,
        float* __restrict__ C, int M, int N, int K, int kChunk,
        const float* __restrict__ rinv) {
    constexpr int NWARP = NT / 32;
    constexpr int WROW = NWARP / WCOL;
    static_assert(WROW * MI * 16 == BM, "BM");
    static_assert(WCOL * NI * 8 == BN, "BN");
    constexpr int PAD = 4;
    __shared__ __align__(16) float As[2][BK][BM + PAD];
    __shared__ __align__(16) float Bs[2][BK][BN + PAD];
    int tid = threadIdx.x;
    int wid = tid >> 5, lane = tid & 31;
    int wm = wid / WCOL, wn = wid % WCOL;
    int g = lane >> 2, tg = lane & 3;
    int m0 = blockIdx.y * BM, n0 = blockIdx.x * BN;
    int k0 = blockIdx.z * kChunk;
    int k1 = min(K, k0 + kChunk);

    constexpr int AV = BM * BK / 4;
    constexpr int BV = BK * BN / 4;
    constexpr int AU = (AV + NT - 1) / NT;
    constexpr int BU = (BV + NT - 1) / NT;
    float4 ar[AU], br[BU];

    auto loadA = [&](int kb) {
#pragma unroll
        for (int u = 0; u < AU; u++) {
            int v = u * NT + tid;
            float4 val = {0.f, 0.f, 0.f, 0.f};
            if (AV % NT == 0 || v < AV) {
                int mm = v / (BK / 4);
                int kk = (v % (BK / 4)) * 4;
                int gm = m0 + mm, gk = kb + kk;
                if (gm < M && gk < k1) {
                    val = *reinterpret_cast<const float4*>(A + (size_t)gm * K + gk);
                    if (SCALE_A) {
                        val.x *= rinv[gk];
                        val.y *= rinv[gk + 1];
                        val.z *= rinv[gk + 2];
                        val.w *= rinv[gk + 3];
                    }
                }
            }
            ar[u] = val;
        }
    };
    auto storeA = [&](int st) {
#pragma unroll
        for (int u = 0; u < AU; u++) {
            int v = u * NT + tid;
            if (AV % NT == 0 || v < AV) {
                int mm = v / (BK / 4);
                int kk = (v % (BK / 4)) * 4;
                As[st][kk + 0][mm] = f2tf(ar[u].x);
                As[st][kk + 1][mm] = f2tf(ar[u].y);
                As[st][kk + 2][mm] = f2tf(ar[u].z);
                As[st][kk + 3][mm] = f2tf(ar[u].w);
            }
        }
    };
    auto loadB = [&](int kb) {
#pragma unroll
        for (int u = 0; u < BU; u++) {
            int v = u * NT + tid;
            float4 val = {0.f, 0.f, 0.f, 0.f};
            if (BV % NT == 0 || v < BV) {
                int kk = v / (BN / 4);
                int nn = (v % (BN / 4)) * 4;
                int gk = kb + kk, gn = n0 + nn;
                if (gk < k1 && gn < N)
                    val = *reinterpret_cast<const float4*>(B + (size_t)gk * N + gn);
            }
            br[u] = val;
        }
    };
    auto storeB = [&](int st) {
#pragma unroll
        for (int u = 0; u < BU; u++) {
            int v = u * NT + tid;
            if (BV % NT == 0 || v < BV) {
                int kk = v / (BN / 4);
                int nn = (v % (BN / 4)) * 4;
                float4 val = br[u];
                val.x = f2tf(val.x);
                val.y = f2tf(val.y);
                val.z = f2tf(val.z);
                val.w = f2tf(val.w);
                *reinterpret_cast<float4*>(&Bs[st][kk][nn]) = val;
            }
        }
    };

    float acc[MI][NI][4];
#pragma unroll
    for (int i = 0; i < MI; i++)
#pragma unroll
        for (int j = 0; j < NI; j++)
#pragma unroll
            for (int q = 0; q < 4; q++) acc[i][j][q] = 0.f;

    int ntiles = (k1 > k0) ? (k1 - k0 + BK - 1) / BK : 0;
    if (ntiles > 0) {
        loadA(k0);
        loadB(k0);
        storeA(0);
        storeB(0);
    }
    int cur = 0;
    for (int t = 0; t < ntiles; t++) {
        __syncthreads();
        bool have_next = (t + 1 < ntiles);
        if (have_next) {
            int kbn = k0 + (t + 1) * BK;
            loadA(kbn);
            loadB(kbn);
        }
#pragma unroll
        for (int k8 = 0; k8 < BK; k8 += 8) {
            uint32_t afr[MI][4];
            uint32_t bfr[NI][2];
#pragma unroll
            for (int mi = 0; mi < MI; mi++) {
                int mb = wm * MI * 16 + mi * 16;
                afr[mi][0] = __float_as_uint(As[cur][k8 + tg][mb + g]);
                afr[mi][1] = __float_as_uint(As[cur][k8 + tg][mb + g + 8]);
                afr[mi][2] = __float_as_uint(As[cur][k8 + tg + 4][mb + g]);
                afr[mi][3] = __float_as_uint(As[cur][k8 + tg + 4][mb + g + 8]);
            }
#pragma unroll
            for (int ni = 0; ni < NI; ni++) {
                int nb = wn * NI * 8 + ni * 8;
                bfr[ni][0] = __float_as_uint(Bs[cur][k8 + tg][nb + g]);
                bfr[ni][1] = __float_as_uint(Bs[cur][k8 + tg + 4][nb + g]);
            }
#pragma unroll
            for (int mi = 0; mi < MI; mi++)
#pragma unroll
                for (int ni = 0; ni < NI; ni++) mma_tf32(acc[mi][ni], afr[mi], bfr[ni]);
        }
        if (have_next) {
            storeA(1 - cur);
            storeB(1 - cur);
            cur ^= 1;
        }
    }

    float* Cp = C + (size_t)blockIdx.z * M * N;
#pragma unroll
    for (int mi = 0; mi < MI; mi++) {
#pragma unroll
        for (int ni = 0; ni < NI; ni++) {
            int r0 = m0 + wm * MI * 16 + mi * 16 + g;
            int c0 = n0 + wn * NI * 8 + ni * 8 + 2 * tg;
#pragma unroll
            for (int half = 0; half < 2; half++) {
                int rr = r0 + half * 8;
                if (rr < M) {
                    float v0 = acc[mi][ni][2 * half];
                    float v1 = acc[mi][ni][2 * half + 1];
                    if (c0 + 1 < N) {
                        float2 v2 = {v0, v1};
                        *reinterpret_cast<float2*>(&Cp[(size_t)rr * N + c0]) = v2;
                    } else if (c0 < N) {
                        Cp[(size_t)rr * N + c0] = v0;
                    }
                }
            }
        }
    }
}

__global__ void k_prep_x0(const float* __restrict__ x) {
    int idx = blockIdx.x * 256 + threadIdx.x;
    if (idx < Nn * BCp) {
        int n = idx / BCp, j = idx % BCp;
        float v = 0.f;
        if (j < BC) {
            int b = j / Cn, c = j % Cn;
            v = x[((size_t)b * Nn + n) * Cn + c];
        }
        g_X0[idx] = v;
    }
}

__global__ void k_reduceY(float* __restrict__ Y) {
    int idx = blockIdx.x * 256 + threadIdx.x;
    if (idx < Nn * BCp) {
        float s = 0.f;
#pragma unroll
        for (int p = 0; p < SPL; p++) s += g_pp[(size_t)p * Nn * BCp + idx];
        Y[idx] = s;
    }
}

// mean / weighted-prefix combos of bootstrap-gathered edge signals
__global__ void k_prep_xe2(const float* __restrict__ xew, const int* __restrict__ bidx,
                           const float* __restrict__ lw, const float* __restrict__ lb) {
    int idx = blockIdx.x * 256 + threadIdx.x;
    if (idx < Bn * En) {
        int b = idx / En, e = idx % En;
        float xs[NBn];
#pragma unroll
        for (int f = 0; f < NBn; f++) {
            int t = bidx[f];
            xs[f] = xew[((size_t)(b * Wn_ + t)) * En + e] * lw[0] + lb[0];
        }
        g_XEu[idx] = (xs[0] + xs[1] + xs[2]) * (1.f / 3.f);
        g_XEv[idx] = (2.f * xs[0] + xs[1]) * (1.f / 3.f);
    }
}

__global__ void k_tsum(const float* __restrict__ xw, const float* __restrict__ Tp) {
    int idx = blockIdx.x * 256 + threadIdx.x;
    if (idx < Bn * Nn) {
        int b = idx / Nn, n = idx % Nn;
        float s = 0.f;
#pragma unroll
        for (int t = 0; t < Wn_; t++) s += xw[((size_t)(b * Wn_ + t)) * Nn + n] * Tp[t];
        g_ts[idx] = s;
    }
}

__global__ void k_rowsum_g(const float* __restrict__ gw) {
    __shared__ float red[256];
    int row = blockIdx.x, tid = threadIdx.x;
    float s = 0.f;
    for (int i = tid; i < Nn; i += 256) s += gw[(size_t)row * Nn + i];
    s = blk_reduce(s, red, false);
    if (tid == 0) g_G[row] = s;
}

// reduce hodge split-K partials + jump*v, write transposed (E,16)
__global__ void k_hreduce(const int* __restrict__ jump_ptr) {
    int e = blockIdx.x * 256 + threadIdx.x;
    int b = blockIdx.y;
    if (e < En) {
        float v = 0.f;
#pragma unroll
        for (int p = 0; p < SPL; p++) v += g_hpart[(size_t)p * Bn * En + b * En + e];
        v += (float)jump_ptr[0] * g_XEv[b * En + e];
        g_XEST[e * Bn + b] = v;
    }
}

__global__ void k_mreduce() {
    int idx = blockIdx.x * 256 + threadIdx.x;
    if (idx < Bn * Nn) {
        int b = idx / Nn, n = idx % Nn;
        float v = 0.f;
#pragma unroll
        for (int p = 0; p < SPLI; p++) v += g_ipart[(size_t)p * Nn * Bn + n * Bn + b];
        g_Mm[idx] = v;
    }
}

// fused per-node epilogue: diffusion conv + ZFC + temporal + supra + bias
__global__ void k_epilogue(const float* __restrict__ x, const float* __restrict__ zin,
                           const float* __restrict__ gnnb, float* __restrict__ out) {
    __shared__ float Wns[KC * O4];
    __shared__ float xs[Bn * 52];
    __shared__ float bias_s[On];
    __shared__ float wwt_s[O2];
    __shared__ float wws_s[O8];
    __shared__ float ts_s[Bn];
    __shared__ float Ms_s[Bn];
    int n = blockIdx.x, tid = threadIdx.x;
    for (int i = tid; i < KC * O4; i += 256) Wns[i] = g_W[(size_t)n * KC * O4 + i];
    for (int i = tid; i < Bn * KC; i += 256) {
        int b = i / KC, kc = i % KC;
        int k = kc / Cn, c = kc % Cn;
        float v;
        if (k == 0) v = x[((size_t)b * Nn + n) * Cn + c];
        else if (k == 1) v = g_Y1[n * BCp + b * Cn + c];
        else v = g_Y2[n * BCp + b * Cn + c];
        xs[b * 52 + kc] = v;
    }
    bias_s[tid] = g_bias[n * On + tid];
    if (tid < O2) wwt_s[tid] = g_wwt[n * O2 + tid];
    if (tid < O8) wws_s[tid] = g_wws[n * O8 + tid];
    if (tid < Bn) {
        ts_s[tid] = g_ts[tid * Nn + n];
        Ms_s[tid] = g_Mm[tid * Nn + n];
    }
    __syncthreads();
    int b = tid >> 4;
    int oc = (tid & 15) * 4;
    ull acc2[2] = {0ull, 0ull};
    for (int kc = 0; kc < KC; kc++) {
        float a = xs[b * 52 + kc];
        ull a2 = pack2(a, a);
        const ull* wp2 = reinterpret_cast<const ull*>(&Wns[kc * O4 + oc]);
        fma2(acc2[0], a2, wp2[0]);
        fma2(acc2[1], a2, wp2[1]);
    }
    float acc[4];
    unpack2(acc[0], acc[1], acc2[0]);
    unpack2(acc[2], acc[3], acc2[1]);
    float* orow = out + ((size_t)b * Nn + n) * On;
#pragma unroll
    for (int j = 0; j < 4; j++) orow[oc + j] = acc[j] + bias_s[oc + j];
#pragma unroll
    for (int it = 0; it < 12; it++) {
        int o = 64 + (tid & 15) + it * 16;
        float v;
        if (o < 96) {
            int c = o - 64;
            int flat = n * O8 + c;
            int i2 = flat / Nn;
            int m = flat - i2 * Nn;
            v = fmaxf(zin[b * O8 + i2] * g_G[m] + gnnb[m], 0.f);
        } else if (o < 224) {
            v = ts_s[b] * wwt_s[o - 96];
        } else {
            v = Ms_s[b] * wws_s[o - 224];
        }
        orow[o] = v + bias_s[o];
    }
}

// ---------------- launch ----------------
extern "C" void kernel_launch(void* const* d_in, const int* in_sizes, int n_in,
                              void* d_out, int out_size) {
    const float* x    = (const float*)d_in[0];
    const float* xw   = (const float*)d_in[1];
    const float* ne   = (const float*)d_in[2];
    const int*   fa   = (const int*)d_in[3];
    const float* adj  = (const float*)d_in[4];
    const int*   stay = (const int*)d_in[5];
    const int*   jump = (const int*)d_in[6];
    const float* zin  = (const float*)d_in[7];
    const float* hodge= (const float*)d_in[8];
    const float* xew  = (const float*)d_in[9];
    const float* inc  = (const float*)d_in[10];
    const float* wp   = (const float*)d_in[11];
    const float* wwsp = (const float*)d_in[12];
    const float* wwtp = (const float*)d_in[13];
    const float* bp   = (const float*)d_in[14];
    const float* Tp   = (const float*)d_in[15];
    const float* lw   = (const float*)d_in[16];
    const float* lb   = (const float*)d_in[17];
    const float* gw   = (const float*)d_in[18];
    const float* gb   = (const float*)d_in[19];
    const int*   bidx = (const int*)d_in[20];
    float* out = (float*)d_out;

    float *pS, *pR, *pW, *pWwt, *pWws, *pBias, *pX0, *pY1, *pY2, *pPP;
    float *pXEu, *pH, *pXEST, *pI;
    cudaGetSymbolAddress((void**)&pS, g_S);
    cudaGetSymbolAddress((void**)&pR, g_r);
    cudaGetSymbolAddress((void**)&pW, g_W);
    cudaGetSymbolAddress((void**)&pWwt, g_wwt);
    cudaGetSymbolAddress((void**)&pWws, g_wws);
    cudaGetSymbolAddress((void**)&pBias, g_bias);
    cudaGetSymbolAddress((void**)&pX0, g_X0);
    cudaGetSymbolAddress((void**)&pY1, g_Y1);
    cudaGetSymbolAddress((void**)&pY2, g_Y2);
    cudaGetSymbolAddress((void**)&pPP, g_pp);
    cudaGetSymbolAddress((void**)&pXEu, g_XEu);
    cudaGetSymbolAddress((void**)&pH, g_hpart);
    cudaGetSymbolAddress((void**)&pXEST, g_XEST);
    cudaGetSymbolAddress((void**)&pI, g_ipart);

    static bool attr_done = false;
    if (!attr_done) {
        cudaFuncSetAttribute(k_S_fused, cudaFuncAttributeMaxDynamicSharedMemorySize, 8 * Nn * 4);
        attr_done = true;
    }

    // S branch: fused relu(ne@neT)+diag -> softmax/adj*exp -> S + 1/rowsum
    k_transpose_ne<<<(Nn * Dn + 255) / 256, 256>>>(ne);
    k_S_fused<<<Nn / 8, 256, 8 * Nn * 4>>>(ne, adj, fa, stay);

    // adaptive params from node embeddings (store-bound outer products)
    k_outer16<<<dim3(13, 16), 256>>>(ne, wp, pW, KC * O4);
    k_outer16<<<dim3(1, 16), 256>>>(ne, bp, pBias, On);
    k_outer16<<<dim3(1, 16), 256>>>(ne, wwtp, pWwt, O2);
    k_outer16<<<dim3(1, 16), 256>>>(ne, wwsp, pWws, O8);

    // diffusion: Y1 = (S/r)@x, Y2 = (S/r)@Y1  (tf32 tensor cores, col-scale fused)
    k_prep_x0<<<(Nn * BCp + 255) / 256, 256>>>(x);
    constexpr int bigChunk = 336;  // mult of BK=16, covers 2000 over 6 planes
    k_tfgemm<128, 96, 16, 4, 4, 3, 256, 1><<<dim3(3, 16, SPL), 256>>>(pS, pX0, pPP, Nn, BCp, Nn, bigChunk, pR);
    k_reduceY<<<(Nn * BCp + 255) / 256, 256>>>(pY1);
    k_tfgemm<128, 96, 16, 4, 4, 3, 256, 1><<<dim3(3, 16, SPL), 256>>>(pS, pY1, pPP, Nn, BCp, Nn, bigChunk, pR);
    k_reduceY<<<(Nn * BCp + 255) / 256, 256>>>(pY2);

    // supra branch (mean-over-frames folded: u@hodge + jump*v, then @ inc^T)
    k_prep_xe2<<<(Bn * En + 255) / 256, 256>>>(xew, bidx, lw, lb);
    constexpr int hChunk = 512;  // mult of BK=32
    k_tfgemm<16, 128, 32, 4, 1, 4, 128, 0><<<dim3(24, 1, SPL), 128>>>(pXEu, hodge, pH, Bn, En, En, hChunk, nullptr);
    k_hreduce<<<dim3((En + 255) / 256, Bn), 256>>>(jump);
    constexpr int iChunk = 320;  // mult of BK=32 (tail guarded by k1)
    k_tfgemm<128, 16, 32, 1, 2, 2, 128, 0><<<dim3(1, 16, SPLI), 128>>>(inc, pXEST, pI, Nn, Bn, En, iChunk, nullptr);
    k_mreduce<<<(Bn * Nn + 255) / 256, 256>>>();

    // temporal + ZFC precompute
    k_tsum<<<(Bn * Nn + 255) / 256, 256>>>(xw, Tp);
    k_rowsum_g<<<Nn, 256>>>(gw);

    // fused epilogue
    k_epilogue<<<Nn, 256>>>(x, zin, gb, out);
}

// round 11
// speedup vs baseline: 1.1264x; 1.1264x over previous
#include <cuda_runtime.h>
#include <cstdint>

typedef unsigned long long ull;

// dims
constexpr int Bn = 16, Nn = 2000, En = 3000, Cn = 17, Wn_ = 12, Dn = 16, On = 256, Kk = 3, NBn = 3;
constexpr int BC = Bn * Cn;   // 272
constexpr int BCp = 288;      // padded column count for diffusion GEMMs
constexpr int KC = Kk * Cn;   // 51
constexpr int O4 = On / 4, O8 = On / 8, O2 = On / 2;
constexpr int SPL = 6;        // split-K planes (diffusion, hodge)
constexpr int SPLI = 10;      // split-K planes (incidence)

#define NEG_HUGE -1e30f

// ---------------- scratch (static device globals; no allocs) ----------------
__device__ float g_neT[Dn * Nn];
__device__ float g_S[(size_t)Nn * Nn];          // 16 MB
__device__ float g_r[Nn];                        // reciprocal row sums
__device__ float g_W[(size_t)Nn * KC * O4];     // 26 MB adaptive weights
__device__ float g_X0[Nn * BCp];
__device__ float g_Y1[Nn * BCp];
__device__ float g_Y2[Nn * BCp];
__device__ float g_pp[(size_t)SPL * Nn * BCp];  // split-K partials (diffusion)
__device__ float g_XEu[Bn * En];
__device__ float g_XEv[Bn * En];
__device__ float g_hpart[SPL * Bn * En];
__device__ float g_XEST[En * Bn];
__device__ float g_ipart[SPLI * Nn * Bn];
__device__ float g_Mm[Bn * Nn];
__device__ float g_G[Nn];
__device__ float g_ts[Bn * Nn];

// ---------------- helpers ----------------
__device__ __forceinline__ void fma2(ull& acc, ull a, ull b) {
    asm("fma.rn.f32x2 %0, %1, %2, %0;" : "+l"(acc) : "l"(a), "l"(b));
}
__device__ __forceinline__ ull pack2(float lo, float hi) {
    ull r;
    asm("mov.b64 %0, {%1,%2};" : "=l"(r) : "f"(lo), "f"(hi));
    return r;
}
__device__ __forceinline__ void unpack2(float& lo, float& hi, ull v) {
    asm("mov.b64 {%0,%1}, %2;" : "=f"(lo), "=f"(hi) : "l"(v));
}
__device__ __forceinline__ float f2tf(float f) {
    uint32_t r;
    asm("cvt.rna.tf32.f32 %0, %1;" : "=r"(r) : "f"(f));
    return __uint_as_float(r);
}
__device__ __forceinline__ void mma_tf32(float* d, const uint32_t* a, const uint32_t* b) {
    asm("mma.sync.aligned.m16n8k8.row.col.f32.tf32.tf32.f32 "
        "{%0,%1,%2,%3}, {%4,%5,%6,%7}, {%8,%9}, {%0,%1,%2,%3};"
        : "+f"(d[0]), "+f"(d[1]), "+f"(d[2]), "+f"(d[3])
        : "r"(a[0]), "r"(a[1]), "r"(a[2]), "r"(a[3]), "r"(b[0]), "r"(b[1]));
}

__device__ __forceinline__ float blk_reduce(float v, float* red, bool do_max) {
    int tid = threadIdx.x;
    red[tid] = v;
    __syncthreads();
#pragma unroll
    for (int s = 128; s > 0; s >>= 1) {
        if (tid < s) red[tid] = do_max ? fmaxf(red[tid], red[tid + s]) : (red[tid] + red[tid + s]);
        __syncthreads();
    }
    float r = red[0];
    __syncthreads();
    return r;
}

// ---------------- kernels ----------------

__global__ void k_transpose_ne(const float* __restrict__ ne) {
    int idx = blockIdx.x * 256 + threadIdx.x;
    if (idx < Nn * Dn) {
        int n = idx >> 4, d = idx & 15;
        g_neT[d * Nn + n] = ne[idx];
    }
}

// Fused S-branch: recompute relu(ne@neT)+diag into smem, softmax (or adj*exp),
// single global write of S + reciprocal rowsums. 8 rows/block, warp-per-row.
__global__ void k_S_fused(const float* __restrict__ ne, const float* __restrict__ adj,
                          const int* __restrict__ fa_ptr, const int* __restrict__ stay_ptr) {
    extern __shared__ float s0s[];  // 8 * Nn floats (64 KB)
    __shared__ float neS[8 * 16];
    int tid = threadIdx.x;
    int r0 = blockIdx.x * 8;
    if (tid < 128) neS[tid] = ne[r0 * 16 + tid];
    __syncthreads();
    float stayv = (float)stay_ptr[0];
    for (int j = tid; j < Nn; j += 256) {
        float nt[16];
#pragma unroll
        for (int d = 0; d < 16; d++) nt[d] = g_neT[d * Nn + j];
#pragma unroll
        for (int r = 0; r < 8; r++) {
            float s = 0.f;
#pragma unroll
            for (int d = 0; d < 16; d++) s += neS[r * 16 + d] * nt[d];
            s = fmaxf(s, 0.f);
            if (r0 + r == j) s = stayv;
            s0s[r * Nn + j] = s;
        }
    }
    __syncthreads();
    int w = tid >> 5, lane = tid & 31;
    int row = r0 + w;
    float* srow_s = s0s + w * Nn;
    float* srow_g = g_S + (size_t)row * Nn;
    if (fa_ptr[0] == 0) {
        float m = NEG_HUGE;
        for (int j = lane; j < Nn; j += 32) m = fmaxf(m, srow_s[j]);
#pragma unroll
        for (int o = 16; o; o >>= 1) m = fmaxf(m, __shfl_xor_sync(0xffffffffu, m, o));
        float z = 0.f;
        for (int j = lane; j < Nn; j += 32) {
            float e = expf(srow_s[j] - m);
            srow_s[j] = e;
            z += e;
        }
#pragma unroll
        for (int o = 16; o; o >>= 1) z += __shfl_xor_sync(0xffffffffu, z, o);
        float inv = 1.f / z;
        float s2 = 0.f;
        for (int j = lane; j < Nn; j += 32) {
            float v = srow_s[j] * inv;
            srow_g[j] = v;
            s2 += v;
        }
#pragma unroll
        for (int o = 16; o; o >>= 1) s2 += __shfl_xor_sync(0xffffffffu, s2, o);
        if (lane == 0) g_r[row] = 1.f / s2;
    } else {
        float s2 = 0.f;
        for (int j = lane; j < Nn; j += 32) {
            float v = adj[(size_t)row * Nn + j] * expf(srow_s[j]);
            srow_g[j] = v;
            s2 += v;
        }
#pragma unroll
        for (int o = 16; o; o >>= 1) s2 += __shfl_xor_sync(0xffffffffu, s2, o);
        if (lane == 0) g_r[row] = 1.f / s2;
    }
}

// Store-bound outer product: C[n,c] = sum_d ne[n,d] * B[d,c]. Ncols % 4 == 0.
__global__ void k_outer16(const float* __restrict__ ne, const float* __restrict__ B,
                          float* __restrict__ C, int Ncols) {
    __shared__ float4 Bs[16][64];
    __shared__ float neS[125 * 16];
    int tid = threadIdx.x;
    int c0 = blockIdx.x * 256, r0 = blockIdx.y * 125;
    for (int i = tid; i < 16 * 64; i += 256) {
        int d = i >> 6, cg = i & 63;
        int c = c0 + cg * 4;
        float4 v = {0.f, 0.f, 0.f, 0.f};
        if (c < Ncols) v = *reinterpret_cast<const float4*>(B + (size_t)d * Ncols + c);
        Bs[d][cg] = v;
    }
    for (int i = tid; i < 125 * 16; i += 256) neS[i] = ne[r0 * 16 + i];
    __syncthreads();
    int tr = tid >> 6, tc = tid & 63;
    int c = c0 + tc * 4;
    if (c >= Ncols) return;
    for (int rr = tr; rr < 125; rr += 4) {
        float4 acc = {0.f, 0.f, 0.f, 0.f};
#pragma unroll
        for (int d = 0; d < 16; d++) {
            float a = neS[rr * 16 + d];
            float4 b = Bs[d][tc];
            acc.x += a * b.x;
            acc.y += a * b.y;
            acc.z += a * b.z;
            acc.w += a * b.w;
        }
        *reinterpret_cast<float4*>(C + (size_t)(r0 + rr) * Ncols + c) = acc;
    }
}

// ---------------- tf32 tensor-core GEMM (m16n8k8), double-buffered, split-K ----
template <int BM, int BN, int BK, int WCOL, int MI, int NI, int NT, int SCALE_A>
__global__ void __launch_bounds__(NT) k_tfgemm(
        const float* __restrict__ A, const float* __restrict__ B,
        float* __restrict__ C, int M, int N, int K, int kChunk,
        const float* __restrict__ rinv) {
    constexpr int NWARP = NT / 32;
    constexpr int WROW = NWARP / WCOL;
    static_assert(WROW * MI * 16 == BM, "BM");
    static_assert(WCOL * NI * 8 == BN, "BN");
    constexpr int PAD = 4;
    __shared__ __align__(16) float As[2][BK][BM + PAD];
    __shared__ __align__(16) float Bs[2][BK][BN + PAD];
    int tid = threadIdx.x;
    int wid = tid >> 5, lane = tid & 31;
    int wm = wid / WCOL, wn = wid % WCOL;
    int g = lane >> 2, tg = lane & 3;
    int m0 = blockIdx.y * BM, n0 = blockIdx.x * BN;
    int k0 = blockIdx.z * kChunk;
    int k1 = min(K, k0 + kChunk);

    constexpr int AV = BM * BK / 4;
    constexpr int BV = BK * BN / 4;
    constexpr int AU = (AV + NT - 1) / NT;
    constexpr int BU = (BV + NT - 1) / NT;
    float4 ar[AU], br[BU];

    auto loadA = [&](int kb) {
#pragma unroll
        for (int u = 0; u < AU; u++) {
            int v = u * NT + tid;
            float4 val = {0.f, 0.f, 0.f, 0.f};
            if (AV % NT == 0 || v < AV) {
                int mm = v / (BK / 4);
                int kk = (v % (BK / 4)) * 4;
                int gm = m0 + mm, gk = kb + kk;
                if (gm < M && gk < k1) {
                    val = *reinterpret_cast<const float4*>(A + (size_t)gm * K + gk);
                    if (SCALE_A) {
                        val.x *= rinv[gk];
                        val.y *= rinv[gk + 1];
                        val.z *= rinv[gk + 2];
                        val.w *= rinv[gk + 3];
                    }
                }
            }
            ar[u] = val;
        }
    };
    auto storeA = [&](int st) {
#pragma unroll
        for (int u = 0; u < AU; u++) {
            int v = u * NT + tid;
            if (AV % NT == 0 || v < AV) {
                int mm = v / (BK / 4);
                int kk = (v % (BK / 4)) * 4;
                As[st][kk + 0][mm] = f2tf(ar[u].x);
                As[st][kk + 1][mm] = f2tf(ar[u].y);
                As[st][kk + 2][mm] = f2tf(ar[u].z);
                As[st][kk + 3][mm] = f2tf(ar[u].w);
            }
        }
    };
    auto loadB = [&](int kb) {
#pragma unroll
        for (int u = 0; u < BU; u++) {
            int v = u * NT + tid;
            float4 val = {0.f, 0.f, 0.f, 0.f};
            if (BV % NT == 0 || v < BV) {
                int kk = v / (BN / 4);
                int nn = (v % (BN / 4)) * 4;
                int gk = kb + kk, gn = n0 + nn;
                if (gk < k1 && gn < N)
                    val = *reinterpret_cast<const float4*>(B + (size_t)gk * N + gn);
            }
            br[u] = val;
        }
    };
    auto storeB = [&](int st) {
#pragma unroll
        for (int u = 0; u < BU; u++) {
            int v = u * NT + tid;
            if (BV % NT == 0 || v < BV) {
                int kk = v / (BN / 4);
                int nn = (v % (BN / 4)) * 4;
                float4 val = br[u];
                val.x = f2tf(val.x);
                val.y = f2tf(val.y);
                val.z = f2tf(val.z);
                val.w = f2tf(val.w);
                *reinterpret_cast<float4*>(&Bs[st][kk][nn]) = val;
            }
        }
    };

    float acc[MI][NI][4];
#pragma unroll
    for (int i = 0; i < MI; i++)
#pragma unroll
        for (int j = 0; j < NI; j++)
#pragma unroll
            for (int q = 0; q < 4; q++) acc[i][j][q] = 0.f;

    int ntiles = (k1 > k0) ? (k1 - k0 + BK - 1) / BK : 0;
    if (ntiles > 0) {
        loadA(k0);
        loadB(k0);
        storeA(0);
        storeB(0);
    }
    int cur = 0;
    for (int t = 0; t < ntiles; t++) {
        __syncthreads();
        bool have_next = (t + 1 < ntiles);
        if (have_next) {
            int kbn = k0 + (t + 1) * BK;
            loadA(kbn);
            loadB(kbn);
        }
#pragma unroll
        for (int k8 = 0; k8 < BK; k8 += 8) {
            uint32_t afr[MI][4];
            uint32_t bfr[NI][2];
#pragma unroll
            for (int mi = 0; mi < MI; mi++) {
                int mb = wm * MI * 16 + mi * 16;
                afr[mi][0] = __float_as_uint(As[cur][k8 + tg][mb + g]);
                afr[mi][1] = __float_as_uint(As[cur][k8 + tg][mb + g + 8]);
                afr[mi][2] = __float_as_uint(As[cur][k8 + tg + 4][mb + g]);
                afr[mi][3] = __float_as_uint(As[cur][k8 + tg + 4][mb + g + 8]);
            }
#pragma unroll
            for (int ni = 0; ni < NI; ni++) {
                int nb = wn * NI * 8 + ni * 8;
                bfr[ni][0] = __float_as_uint(Bs[cur][k8 + tg][nb + g]);
                bfr[ni][1] = __float_as_uint(Bs[cur][k8 + tg + 4][nb + g]);
            }
#pragma unroll
            for (int mi = 0; mi < MI; mi++)
#pragma unroll
                for (int ni = 0; ni < NI; ni++) mma_tf32(acc[mi][ni], afr[mi], bfr[ni]);
        }
        if (have_next) {
            storeA(1 - cur);
            storeB(1 - cur);
            cur ^= 1;
        }
    }

    float* Cp = C + (size_t)blockIdx.z * M * N;
#pragma unroll
    for (int mi = 0; mi < MI; mi++) {
#pragma unroll
        for (int ni = 0; ni < NI; ni++) {
            int r0 = m0 + wm * MI * 16 + mi * 16 + g;
            int c0 = n0 + wn * NI * 8 + ni * 8 + 2 * tg;
#pragma unroll
            for (int half = 0; half < 2; half++) {
                int rr = r0 + half * 8;
                if (rr < M) {
                    float v0 = acc[mi][ni][2 * half];
                    float v1 = acc[mi][ni][2 * half + 1];
                    if (c0 + 1 < N) {
                        float2 v2 = {v0, v1};
                        *reinterpret_cast<float2*>(&Cp[(size_t)rr * N + c0]) = v2;
                    } else if (c0 < N) {
                        Cp[(size_t)rr * N + c0] = v0;
                    }
                }
            }
        }
    }
}

__global__ void k_prep_x0(const float* __restrict__ x) {
    int idx = blockIdx.x * 256 + threadIdx.x;
    if (idx < Nn * BCp) {
        int n = idx / BCp, j = idx % BCp;
        float v = 0.f;
        if (j < BC) {
            int b = j / Cn, c = j % Cn;
            v = x[((size_t)b * Nn + n) * Cn + c];
        }
        g_X0[idx] = v;
    }
}

__global__ void k_reduceY(float* __restrict__ Y) {
    int idx = blockIdx.x * 256 + threadIdx.x;
    if (idx < Nn * BCp) {
        float s = 0.f;
#pragma unroll
        for (int p = 0; p < SPL; p++) s += g_pp[(size_t)p * Nn * BCp + idx];
        Y[idx] = s;
    }
}

// mean / weighted-prefix combos of bootstrap-gathered edge signals
__global__ void k_prep_xe2(const float* __restrict__ xew, const int* __restrict__ bidx,
                           const float* __restrict__ lw, const float* __restrict__ lb) {
    int idx = blockIdx.x * 256 + threadIdx.x;
    if (idx < Bn * En) {
        int b = idx / En, e = idx % En;
        float xs[NBn];
#pragma unroll
        for (int f = 0; f < NBn; f++) {
            int t = bidx[f];
            xs[f] = xew[((size_t)(b * Wn_ + t)) * En + e] * lw[0] + lb[0];
        }
        g_XEu[idx] = (xs[0] + xs[1] + xs[2]) * (1.f / 3.f);
        g_XEv[idx] = (2.f * xs[0] + xs[1]) * (1.f / 3.f);
    }
}

__global__ void k_tsum(const float* __restrict__ xw, const float* __restrict__ Tp) {
    int idx = blockIdx.x * 256 + threadIdx.x;
    if (idx < Bn * Nn) {
        int b = idx / Nn, n = idx % Nn;
        float s = 0.f;
#pragma unroll
        for (int t = 0; t < Wn_; t++) s += xw[((size_t)(b * Wn_ + t)) * Nn + n] * Tp[t];
        g_ts[idx] = s;
    }
}

__global__ void k_rowsum_g(const float* __restrict__ gw) {
    __shared__ float red[256];
    int row = blockIdx.x, tid = threadIdx.x;
    float s = 0.f;
    for (int i = tid; i < Nn; i += 256) s += gw[(size_t)row * Nn + i];
    s = blk_reduce(s, red, false);
    if (tid == 0) g_G[row] = s;
}

// reduce hodge split-K partials + jump*v, write transposed (E,16)
__global__ void k_hreduce(const int* __restrict__ jump_ptr) {
    int e = blockIdx.x * 256 + threadIdx.x;
    int b = blockIdx.y;
    if (e < En) {
        float v = 0.f;
#pragma unroll
        for (int p = 0; p < SPL; p++) v += g_hpart[(size_t)p * Bn * En + b * En + e];
        v += (float)jump_ptr[0] * g_XEv[b * En + e];
        g_XEST[e * Bn + b] = v;
    }
}

__global__ void k_mreduce() {
    int idx = blockIdx.x * 256 + threadIdx.x;
    if (idx < Bn * Nn) {
        int b = idx / Nn, n = idx % Nn;
        float v = 0.f;
#pragma unroll
        for (int p = 0; p < SPLI; p++) v += g_ipart[(size_t)p * Nn * Bn + n * Bn + b];
        g_Mm[idx] = v;
    }
}

// fused per-node epilogue: diffusion conv + ZFC + temporal + supra + bias.
// bias/wwt/wws are computed in-block from ne and the pools (no precompute kernels).
__global__ void k_epilogue(const float* __restrict__ x, const float* __restrict__ zin,
                           const float* __restrict__ gnnb, const float* __restrict__ ne,
                           const float* __restrict__ bp, const float* __restrict__ wwtp,
                           const float* __restrict__ wwsp, float* __restrict__ out) {
    __shared__ float Wns[KC * O4];
    __shared__ float xs[Bn * 52];
    __shared__ float bias_s[On];
    __shared__ float wwt_s[O2];
    __shared__ float wws_s[O8];
    __shared__ float ts_s[Bn];
    __shared__ float Ms_s[Bn];
    __shared__ float ne_s[16];
    int n = blockIdx.x, tid = threadIdx.x;
    if (tid < 16) ne_s[tid] = ne[n * 16 + tid];
    for (int i = tid; i < KC * O4; i += 256) Wns[i] = g_W[(size_t)n * KC * O4 + i];
    for (int i = tid; i < Bn * KC; i += 256) {
        int b = i / KC, kc = i % KC;
        int k = kc / Cn, c = kc % Cn;
        float v;
        if (k == 0) v = x[((size_t)b * Nn + n) * Cn + c];
        else if (k == 1) v = g_Y1[n * BCp + b * Cn + c];
        else v = g_Y2[n * BCp + b * Cn + c];
        xs[b * 52 + kc] = v;
    }
    if (tid < Bn) {
        ts_s[tid] = g_ts[tid * Nn + n];
        Ms_s[tid] = g_Mm[tid * Nn + n];
    }
    __syncthreads();
    // per-node adaptive params from pools (L2-resident broadcasts)
    {
        float b_acc = 0.f;
#pragma unroll
        for (int d = 0; d < 16; d++) b_acc += ne_s[d] * bp[d * On + tid];
        bias_s[tid] = b_acc;
        if (tid < O2) {
            float w_acc = 0.f;
#pragma unroll
            for (int d = 0; d < 16; d++) w_acc += ne_s[d] * wwtp[d * O2 + tid];
            wwt_s[tid] = w_acc;
        }
        if (tid < O8) {
            float w_acc = 0.f;
#pragma unroll
            for (int d = 0; d < 16; d++) w_acc += ne_s[d] * wwsp[d * O8 + tid];
            wws_s[tid] = w_acc;
        }
    }
    __syncthreads();
    int b = tid >> 4;
    int oc = (tid & 15) * 4;
    ull acc2[2] = {0ull, 0ull};
    for (int kc = 0; kc < KC; kc++) {
        float a = xs[b * 52 + kc];
        ull a2 = pack2(a, a);
        const ull* wp2 = reinterpret_cast<const ull*>(&Wns[kc * O4 + oc]);
        fma2(acc2[0], a2, wp2[0]);
        fma2(acc2[1], a2, wp2[1]);
    }
    float acc[4];
    unpack2(acc[0], acc[1], acc2[0]);
    unpack2(acc[2], acc[3], acc2[1]);
    float* orow = out + ((size_t)b * Nn + n) * On;
#pragma unroll
    for (int j = 0; j < 4; j++) orow[oc + j] = acc[j] + bias_s[oc + j];
#pragma unroll
    for (int it = 0; it < 12; it++) {
        int o = 64 + (tid & 15) + it * 16;
        float v;
        if (o < 96) {
            int c = o - 64;
            int flat = n * O8 + c;
            int i2 = flat / Nn;
            int m = flat - i2 * Nn;
            v = fmaxf(zin[b * O8 + i2] * g_G[m] + gnnb[m], 0.f);
        } else if (o < 224) {
            v = ts_s[b] * wwt_s[o - 96];
        } else {
            v = Ms_s[b] * wws_s[o - 224];
        }
        orow[o] = v + bias_s[o];
    }
}

// ---------------- launch ----------------
extern "C" void kernel_launch(void* const* d_in, const int* in_sizes, int n_in,
                              void* d_out, int out_size) {
    const float* x    = (const float*)d_in[0];
    const float* xw   = (const float*)d_in[1];
    const float* ne   = (const float*)d_in[2];
    const int*   fa   = (const int*)d_in[3];
    const float* adj  = (const float*)d_in[4];
    const int*   stay = (const int*)d_in[5];
    const int*   jump = (const int*)d_in[6];
    const float* zin  = (const float*)d_in[7];
    const float* hodge= (const float*)d_in[8];
    const float* xew  = (const float*)d_in[9];
    const float* inc  = (const float*)d_in[10];
    const float* wp   = (const float*)d_in[11];
    const float* wwsp = (const float*)d_in[12];
    const float* wwtp = (const float*)d_in[13];
    const float* bp   = (const float*)d_in[14];
    const float* Tp   = (const float*)d_in[15];
    const float* lw   = (const float*)d_in[16];
    const float* lb   = (const float*)d_in[17];
    const float* gw   = (const float*)d_in[18];
    const float* gb   = (const float*)d_in[19];
    const int*   bidx = (const int*)d_in[20];
    float* out = (float*)d_out;

    float *pS, *pR, *pW, *pX0, *pY1, *pY2, *pPP;
    float *pXEu, *pH, *pXEST, *pI;
    cudaGetSymbolAddress((void**)&pS, g_S);
    cudaGetSymbolAddress((void**)&pR, g_r);
    cudaGetSymbolAddress((void**)&pW, g_W);
    cudaGetSymbolAddress((void**)&pX0, g_X0);
    cudaGetSymbolAddress((void**)&pY1, g_Y1);
    cudaGetSymbolAddress((void**)&pY2, g_Y2);
    cudaGetSymbolAddress((void**)&pPP, g_pp);
    cudaGetSymbolAddress((void**)&pXEu, g_XEu);
    cudaGetSymbolAddress((void**)&pH, g_hpart);
    cudaGetSymbolAddress((void**)&pXEST, g_XEST);
    cudaGetSymbolAddress((void**)&pI, g_ipart);

    static bool attr_done = false;
    if (!attr_done) {
        cudaFuncSetAttribute(k_S_fused, cudaFuncAttributeMaxDynamicSharedMemorySize, 8 * Nn * 4);
        attr_done = true;
    }

    // S branch: fused relu(ne@neT)+diag -> softmax/adj*exp -> S + 1/rowsum
    k_transpose_ne<<<(Nn * Dn + 255) / 256, 256>>>(ne);
    k_S_fused<<<Nn / 8, 256, 8 * Nn * 4>>>(ne, adj, fa, stay);

    // adaptive weights (store-bound outer product); bias/wwt/wws folded into epilogue
    k_outer16<<<dim3(13, 16), 256>>>(ne, wp, pW, KC * O4);

    // diffusion: Y1 = (S/r)@x, Y2 = (S/r)@Y1  (tf32 tensor cores, col-scale fused)
    k_prep_x0<<<(Nn * BCp + 255) / 256, 256>>>(x);
    constexpr int bigChunk = 336;  // mult of BK=16, covers 2000 over 6 planes
    k_tfgemm<128, 96, 16, 4, 4, 3, 256, 1><<<dim3(3, 16, SPL), 256>>>(pS, pX0, pPP, Nn, BCp, Nn, bigChunk, pR);
    k_reduceY<<<(Nn * BCp + 255) / 256, 256>>>(pY1);
    k_tfgemm<128, 96, 16, 4, 4, 3, 256, 1><<<dim3(3, 16, SPL), 256>>>(pS, pY1, pPP, Nn, BCp, Nn, bigChunk, pR);
    k_reduceY<<<(Nn * BCp + 255) / 256, 256>>>(pY2);

    // supra branch (mean-over-frames folded: u@hodge + jump*v, then @ inc^T)
    k_prep_xe2<<<(Bn * En + 255) / 256, 256>>>(xew, bidx, lw, lb);
    constexpr int hChunk = 512;  // mult of BK=32
    k_tfgemm<16, 128, 32, 4, 1, 4, 128, 0><<<dim3(24, 1, SPL), 128>>>(pXEu, hodge, pH, Bn, En, En, hChunk, nullptr);
    k_hreduce<<<dim3((En + 255) / 256, Bn), 256>>>(jump);
    constexpr int iChunk = 320;  // mult of BK=32 (tail guarded by k1)
    k_tfgemm<128, 16, 32, 1, 2, 2, 128, 0><<<dim3(1, 16, SPLI), 128>>>(inc, pXEST, pI, Nn, Bn, En, iChunk, nullptr);
    k_mreduce<<<(Bn * Nn + 255) / 256, 256>>>();

    // temporal + ZFC precompute
    k_tsum<<<(Bn * Nn + 255) / 256, 256>>>(xw, Tp);
    k_rowsum_g<<<Nn, 256>>>(gw);

    // fused epilogue (computes bias/wwt/wws in-block)
    k_epilogue<<<Nn, 256>>>(x, zin, gb, ne, bp, wwtp, wwsp, out);
}

// round 14
// speedup vs baseline: 1.4423x; 1.2804x over previous
#include <cuda_runtime.h>
#include <cstdint>

typedef unsigned long long ull;

// dims
constexpr int Bn = 16, Nn = 2000, En = 3000, Cn = 17, Wn_ = 12, Dn = 16, On = 256, Kk = 3, NBn = 3;
constexpr int BC = Bn * Cn;   // 272
constexpr int BCp = 288;      // padded column count for diffusion GEMMs
constexpr int KC = Kk * Cn;   // 51
constexpr int O4 = On / 4, O8 = On / 8, O2 = On / 2;
constexpr int SPL = 6;        // split-K planes (diffusion, hodge)
constexpr int SPLI = 10;      // split-K planes (incidence)

#define NEG_HUGE -1e30f

// ---------------- scratch (static device globals; no allocs) ----------------
__device__ float g_neT[Dn * Nn];
__device__ float g_S[(size_t)Nn * Nn];          // 16 MB
__device__ float g_r[Nn];                        // reciprocal row sums
__device__ float g_W[(size_t)Nn * KC * O4];     // 26 MB adaptive weights
__device__ float g_X0[Nn * BCp];
__device__ float g_Y1[Nn * BCp];
__device__ float g_pp[(size_t)SPL * Nn * BCp];  // split-K partials (diffusion)
__device__ float g_XEu[Bn * En];
__device__ float g_XEv[Bn * En];
__device__ float g_hpart[SPL * Bn * En];
__device__ float g_XEST[En * Bn];
__device__ float g_ipart[SPLI * Nn * Bn];
__device__ float g_Mm[Bn * Nn];
__device__ float g_G[Nn];
__device__ float g_ts[Bn * Nn];

// ---------------- helpers ----------------
__device__ __forceinline__ void fma2(ull& acc, ull a, ull b) {
    asm("fma.rn.f32x2 %0, %1, %2, %0;" : "+l"(acc) : "l"(a), "l"(b));
}
__device__ __forceinline__ ull pack2(float lo, float hi) {
    ull r;
    asm("mov.b64 %0, {%1,%2};" : "=l"(r) : "f"(lo), "f"(hi));
    return r;
}
__device__ __forceinline__ void unpack2(float& lo, float& hi, ull v) {
    asm("mov.b64 {%0,%1}, %2;" : "=f"(lo), "=f"(hi) : "l"(v));
}
__device__ __forceinline__ float f2tf(float f) {
    uint32_t r;
    asm("cvt.rna.tf32.f32 %0, %1;" : "=r"(r) : "f"(f));
    return __uint_as_float(r);
}
__device__ __forceinline__ void mma_tf32(float* d, const uint32_t* a, const uint32_t* b) {
    asm("mma.sync.aligned.m16n8k8.row.col.f32.tf32.tf32.f32 "
        "{%0,%1,%2,%3}, {%4,%5,%6,%7}, {%8,%9}, {%0,%1,%2,%3};"
        : "+f"(d[0]), "+f"(d[1]), "+f"(d[2]), "+f"(d[3])
        : "r"(a[0]), "r"(a[1]), "r"(a[2]), "r"(a[3]), "r"(b[0]), "r"(b[1]));
}

__device__ __forceinline__ float blk_reduce(float v, float* red, bool do_max) {
    int tid = threadIdx.x;
    red[tid] = v;
    __syncthreads();
#pragma unroll
    for (int s = 128; s > 0; s >>= 1) {
        if (tid < s) red[tid] = do_max ? fmaxf(red[tid], red[tid + s]) : (red[tid] + red[tid + s]);
        __syncthreads();
    }
    float r = red[0];
    __syncthreads();
    return r;
}

// ---------------- kernels ----------------

__global__ void k_transpose_ne(const float* __restrict__ ne) {
    int idx = blockIdx.x * 256 + threadIdx.x;
    if (idx < Nn * Dn) {
        int n = idx >> 4, d = idx & 15;
        g_neT[d * Nn + n] = ne[idx];
    }
}

// Fused S-branch: recompute relu(ne@neT)+diag into smem, softmax (or adj*exp),
// single global write of S + reciprocal rowsums. 8 rows/block, warp-per-row.
__global__ void k_S_fused(const float* __restrict__ ne, const float* __restrict__ adj,
                          const int* __restrict__ fa_ptr, const int* __restrict__ stay_ptr) {
    extern __shared__ float s0s[];  // 8 * Nn floats (64 KB)
    __shared__ float neS[8 * 16];
    int tid = threadIdx.x;
    int r0 = blockIdx.x * 8;
    if (tid < 128) neS[tid] = ne[r0 * 16 + tid];
    __syncthreads();
    float stayv = (float)stay_ptr[0];
    for (int j = tid; j < Nn; j += 256) {
        float nt[16];
#pragma unroll
        for (int d = 0; d < 16; d++) nt[d] = g_neT[d * Nn + j];
#pragma unroll
        for (int r = 0; r < 8; r++) {
            float s = 0.f;
#pragma unroll
            for (int d = 0; d < 16; d++) s += neS[r * 16 + d] * nt[d];
            s = fmaxf(s, 0.f);
            if (r0 + r == j) s = stayv;
            s0s[r * Nn + j] = s;
        }
    }
    __syncthreads();
    int w = tid >> 5, lane = tid & 31;
    int row = r0 + w;
    float* srow_s = s0s + w * Nn;
    float* srow_g = g_S + (size_t)row * Nn;
    if (fa_ptr[0] == 0) {
        float m = NEG_HUGE;
        for (int j = lane; j < Nn; j += 32) m = fmaxf(m, srow_s[j]);
#pragma unroll
        for (int o = 16; o; o >>= 1) m = fmaxf(m, __shfl_xor_sync(0xffffffffu, m, o));
        float z = 0.f;
        for (int j = lane; j < Nn; j += 32) {
            float e = expf(srow_s[j] - m);
            srow_s[j] = e;
            z += e;
        }
#pragma unroll
        for (int o = 16; o; o >>= 1) z += __shfl_xor_sync(0xffffffffu, z, o);
        float inv = 1.f / z;
        float s2 = 0.f;
        for (int j = lane; j < Nn; j += 32) {
            float v = srow_s[j] * inv;
            srow_g[j] = v;
            s2 += v;
        }
#pragma unroll
        for (int o = 16; o; o >>= 1) s2 += __shfl_xor_sync(0xffffffffu, s2, o);
        if (lane == 0) g_r[row] = 1.f / s2;
    } else {
        float s2 = 0.f;
        for (int j = lane; j < Nn; j += 32) {
            float v = adj[(size_t)row * Nn + j] * expf(srow_s[j]);
            srow_g[j] = v;
            s2 += v;
        }
#pragma unroll
        for (int o = 16; o; o >>= 1) s2 += __shfl_xor_sync(0xffffffffu, s2, o);
        if (lane == 0) g_r[row] = 1.f / s2;
    }
}

// Store-bound outer product: C[n,c] = sum_d ne[n,d] * B[d,c]. Ncols % 4 == 0.
__global__ void k_outer16(const float* __restrict__ ne, const float* __restrict__ B,
                          float* __restrict__ C, int Ncols) {
    __shared__ float4 Bs[16][64];
    __shared__ float neS[125 * 16];
    int tid = threadIdx.x;
    int c0 = blockIdx.x * 256, r0 = blockIdx.y * 125;
    for (int i = tid; i < 16 * 64; i += 256) {
        int d = i >> 6, cg = i & 63;
        int c = c0 + cg * 4;
        float4 v = {0.f, 0.f, 0.f, 0.f};
        if (c < Ncols) v = *reinterpret_cast<const float4*>(B + (size_t)d * Ncols + c);
        Bs[d][cg] = v;
    }
    for (int i = tid; i < 125 * 16; i += 256) neS[i] = ne[r0 * 16 + i];
    __syncthreads();
    int tr = tid >> 6, tc = tid & 63;
    int c = c0 + tc * 4;
    if (c >= Ncols) return;
    for (int rr = tr; rr < 125; rr += 4) {
        float4 acc = {0.f, 0.f, 0.f, 0.f};
#pragma unroll
        for (int d = 0; d < 16; d++) {
            float a = neS[rr * 16 + d];
            float4 b = Bs[d][tc];
            acc.x += a * b.x;
            acc.y += a * b.y;
            acc.z += a * b.z;
            acc.w += a * b.w;
        }
        *reinterpret_cast<float4*>(C + (size_t)(r0 + rr) * Ncols + c) = acc;
    }
}

// ---------------- tf32 tensor-core GEMM (m16n8k8), double-buffered, split-K ----
template <int BM, int BN, int BK, int WCOL, int MI, int NI, int NT, int SCALE_A>
__global__ void __launch_bounds__(NT) k_tfgemm(
        const float* __restrict__ A, const float* __restrict__ B,
        float* __restrict__ C, int M, int N, int K, int kChunk,
        const float* __restrict__ rinv) {
    constexpr int NWARP = NT / 32;
    constexpr int WROW = NWARP / WCOL;
    static_assert(WROW * MI * 16 == BM, "BM");
    static_assert(WCOL * NI * 8 == BN, "BN");
    constexpr int PAD = 4;
    __shared__ __align__(16) float As[2][BK][BM + PAD];
    __shared__ __align__(16) float Bs[2][BK][BN + PAD];
    int tid = threadIdx.x;
    int wid = tid >> 5, lane = tid & 31;
    int wm = wid / WCOL, wn = wid % WCOL;
    int g = lane >> 2, tg = lane & 3;
    int m0 = blockIdx.y * BM, n0 = blockIdx.x * BN;
    int k0 = blockIdx.z * kChunk;
    int k1 = min(K, k0 + kChunk);

    constexpr int AV = BM * BK / 4;
    constexpr int BV = BK * BN / 4;
    constexpr int AU = (AV + NT - 1) / NT;
    constexpr int BU = (BV + NT - 1) / NT;
    float4 ar[AU], br[BU];

    auto loadA = [&](int kb) {
#pragma unroll
        for (int u = 0; u < AU; u++) {
            int v = u * NT + tid;
            float4 val = {0.f, 0.f, 0.f, 0.f};
            if (AV % NT == 0 || v < AV) {
                int mm = v / (BK / 4);
                int kk = (v % (BK / 4)) * 4;
                int gm = m0 + mm, gk = kb + kk;
                if (gm < M && gk < k1) {
                    val = *reinterpret_cast<const float4*>(A + (size_t)gm * K + gk);
                    if (SCALE_A) {
                        val.x *= rinv[gk];
                        val.y *= rinv[gk + 1];
                        val.z *= rinv[gk + 2];
                        val.w *= rinv[gk + 3];
                    }
                }
            }
            ar[u] = val;
        }
    };
    auto storeA = [&](int st) {
#pragma unroll
        for (int u = 0; u < AU; u++) {
            int v = u * NT + tid;
            if (AV % NT == 0 || v < AV) {
                int mm = v / (BK / 4);
                int kk = (v % (BK / 4)) * 4;
                As[st][kk + 0][mm] = f2tf(ar[u].x);
                As[st][kk + 1][mm] = f2tf(ar[u].y);
                As[st][kk + 2][mm] = f2tf(ar[u].z);
                As[st][kk + 3][mm] = f2tf(ar[u].w);
            }
        }
    };
    auto loadB = [&](int kb) {
#pragma unroll
        for (int u = 0; u < BU; u++) {
            int v = u * NT + tid;
            float4 val = {0.f, 0.f, 0.f, 0.f};
            if (BV % NT == 0 || v < BV) {
                int kk = v / (BN / 4);
                int nn = (v % (BN / 4)) * 4;
                int gk = kb + kk, gn = n0 + nn;
                if (gk < k1 && gn < N)
                    val = *reinterpret_cast<const float4*>(B + (size_t)gk * N + gn);
            }
            br[u] = val;
        }
    };
    auto storeB = [&](int st) {
#pragma unroll
        for (int u = 0; u < BU; u++) {
            int v = u * NT + tid;
            if (BV % NT == 0 || v < BV) {
                int kk = v / (BN / 4);
                int nn = (v % (BN / 4)) * 4;
                float4 val = br[u];
                val.x = f2tf(val.x);
                val.y = f2tf(val.y);
                val.z = f2tf(val.z);
                val.w = f2tf(val.w);
                *reinterpret_cast<float4*>(&Bs[st][kk][nn]) = val;
            }
        }
    };

    float acc[MI][NI][4];
#pragma unroll
    for (int i = 0; i < MI; i++)
#pragma unroll
        for (int j = 0; j < NI; j++)
#pragma unroll
            for (int q = 0; q < 4; q++) acc[i][j][q] = 0.f;

    int ntiles = (k1 > k0) ? (k1 - k0 + BK - 1) / BK : 0;
    if (ntiles > 0) {
        loadA(k0);
        loadB(k0);
        storeA(0);
        storeB(0);
    }
    int cur = 0;
    for (int t = 0; t < ntiles; t++) {
        __syncthreads();
        bool have_next = (t + 1 < ntiles);
        if (have_next) {
            int kbn = k0 + (t + 1) * BK;
            loadA(kbn);
            loadB(kbn);
        }
#pragma unroll
        for (int k8 = 0; k8 < BK; k8 += 8) {
            uint32_t afr[MI][4];
            uint32_t bfr[NI][2];
#pragma unroll
            for (int mi = 0; mi < MI; mi++) {
                int mb = wm * MI * 16 + mi * 16;
                afr[mi][0] = __float_as_uint(As[cur][k8 + tg][mb + g]);
                afr[mi][1] = __float_as_uint(As[cur][k8 + tg][mb + g + 8]);
                afr[mi][2] = __float_as_uint(As[cur][k8 + tg + 4][mb + g]);
                afr[mi][3] = __float_as_uint(As[cur][k8 + tg + 4][mb + g + 8]);
            }
#pragma unroll
            for (int ni = 0; ni < NI; ni++) {
                int nb = wn * NI * 8 + ni * 8;
                bfr[ni][0] = __float_as_uint(Bs[cur][k8 + tg][nb + g]);
                bfr[ni][1] = __float_as_uint(Bs[cur][k8 + tg + 4][nb + g]);
            }
#pragma unroll
            for (int mi = 0; mi < MI; mi++)
#pragma unroll
                for (int ni = 0; ni < NI; ni++) mma_tf32(acc[mi][ni], afr[mi], bfr[ni]);
        }
        if (have_next) {
            storeA(1 - cur);
            storeB(1 - cur);
            cur ^= 1;
        }
    }

    float* Cp = C + (size_t)blockIdx.z * M * N;
#pragma unroll
    for (int mi = 0; mi < MI; mi++) {
#pragma unroll
        for (int ni = 0; ni < NI; ni++) {
            int r0 = m0 + wm * MI * 16 + mi * 16 + g;
            int c0 = n0 + wn * NI * 8 + ni * 8 + 2 * tg;
#pragma unroll
            for (int half = 0; half < 2; half++) {
                int rr = r0 + half * 8;
                if (rr < M) {
                    float v0 = acc[mi][ni][2 * half];
                    float v1 = acc[mi][ni][2 * half + 1];
                    if (c0 + 1 < N) {
                        float2 v2 = {v0, v1};
                        *reinterpret_cast<float2*>(&Cp[(size_t)rr * N + c0]) = v2;
                    } else if (c0 < N) {
                        Cp[(size_t)rr * N + c0] = v0;
                    }
                }
            }
        }
    }
}

__global__ void k_prep_x0(const float* __restrict__ x) {
    int idx = blockIdx.x * 256 + threadIdx.x;
    if (idx < Nn * BCp) {
        int n = idx / BCp, j = idx % BCp;
        float v = 0.f;
        if (j < BC) {
            int b = j / Cn, c = j % Cn;
            v = x[((size_t)b * Nn + n) * Cn + c];
        }
        g_X0[idx] = v;
    }
}

__global__ void k_reduceY(float* __restrict__ Y) {
    int idx = blockIdx.x * 256 + threadIdx.x;
    if (idx < Nn * BCp) {
        float s = 0.f;
#pragma unroll
        for (int p = 0; p < SPL; p++) s += g_pp[(size_t)p * Nn * BCp + idx];
        Y[idx] = s;
    }
}

// mean / weighted-prefix combos of bootstrap-gathered edge signals
__global__ void k_prep_xe2(const float* __restrict__ xew, const int* __restrict__ bidx,
                           const float* __restrict__ lw, const float* __restrict__ lb) {
    int idx = blockIdx.x * 256 + threadIdx.x;
    if (idx < Bn * En) {
        int b = idx / En, e = idx % En;
        float xs[NBn];
#pragma unroll
        for (int f = 0; f < NBn; f++) {
            int t = bidx[f];
            xs[f] = xew[((size_t)(b * Wn_ + t)) * En + e] * lw[0] + lb[0];
        }
        g_XEu[idx] = (xs[0] + xs[1] + xs[2]) * (1.f / 3.f);
        g_XEv[idx] = (2.f * xs[0] + xs[1]) * (1.f / 3.f);
    }
}

__global__ void k_tsum(const float* __restrict__ xw, const float* __restrict__ Tp) {
    int idx = blockIdx.x * 256 + threadIdx.x;
    if (idx < Bn * Nn) {
        int b = idx / Nn, n = idx % Nn;
        float s = 0.f;
#pragma unroll
        for (int t = 0; t < Wn_; t++) s += xw[((size_t)(b * Wn_ + t)) * Nn + n] * Tp[t];
        g_ts[idx] = s;
    }
}

__global__ void k_rowsum_g(const float* __restrict__ gw) {
    __shared__ float red[256];
    int row = blockIdx.x, tid = threadIdx.x;
    float s = 0.f;
    for (int i = tid; i < Nn; i += 256) s += gw[(size_t)row * Nn + i];
    s = blk_reduce(s, red, false);
    if (tid == 0) g_G[row] = s;
}

// reduce hodge split-K partials + jump*v, write transposed (E,16)
__global__ void k_hreduce(const int* __restrict__ jump_ptr) {
    int e = blockIdx.x * 256 + threadIdx.x;
    int b = blockIdx.y;
    if (e < En) {
        float v = 0.f;
#pragma unroll
        for (int p = 0; p < SPL; p++) v += g_hpart[(size_t)p * Bn * En + b * En + e];
        v += (float)jump_ptr[0] * g_XEv[b * En + e];
        g_XEST[e * Bn + b] = v;
    }
}

__global__ void k_mreduce() {
    int idx = blockIdx.x * 256 + threadIdx.x;
    if (idx < Bn * Nn) {
        int b = idx / Nn, n = idx % Nn;
        float v = 0.f;
#pragma unroll
        for (int p = 0; p < SPLI; p++) v += g_ipart[(size_t)p * Nn * Bn + n * Bn + b];
        g_Mm[idx] = v;
    }
}

// fused per-node epilogue: diffusion conv + ZFC + temporal + supra + bias.
// bias/wwt/wws computed in-block; Y2 summed from split-K partials in-block.
__global__ void k_epilogue(const float* __restrict__ x, const float* __restrict__ zin,
                           const float* __restrict__ gnnb, const float* __restrict__ ne,
                           const float* __restrict__ bp, const float* __restrict__ wwtp,
                           const float* __restrict__ wwsp, float* __restrict__ out) {
    __shared__ float Wns[KC * O4];
    __shared__ float xs[Bn * 52];
    __shared__ float bias_s[On];
    __shared__ float wwt_s[O2];
    __shared__ float wws_s[O8];
    __shared__ float ts_s[Bn];
    __shared__ float Ms_s[Bn];
    __shared__ float ne_s[16];
    int n = blockIdx.x, tid = threadIdx.x;
    if (tid < 16) ne_s[tid] = ne[n * 16 + tid];
    for (int i = tid; i < KC * O4; i += 256) Wns[i] = g_W[(size_t)n * KC * O4 + i];
    for (int i = tid; i < Bn * KC; i += 256) {
        int b = i / KC, kc = i % KC;
        int k = kc / Cn, c = kc % Cn;
        float v;
        if (k == 0) v = x[((size_t)b * Nn + n) * Cn + c];
        else if (k == 1) v = g_Y1[n * BCp + b * Cn + c];
        else {
            v = 0.f;
#pragma unroll
            for (int p = 0; p < SPL; p++) v += g_pp[(size_t)p * Nn * BCp + n * BCp + b * Cn + c];
        }
        xs[b * 52 + kc] = v;
    }
    if (tid < Bn) {
        ts_s[tid] = g_ts[tid * Nn + n];
        Ms_s[tid] = g_Mm[tid * Nn + n];
    }
    __syncthreads();
    // per-node adaptive params from pools (L2-resident broadcasts)
    {
        float b_acc = 0.f;
#pragma unroll
        for (int d = 0; d < 16; d++) b_acc += ne_s[d] * bp[d * On + tid];
        bias_s[tid] = b_acc;
        if (tid < O2) {
            float w_acc = 0.f;
#pragma unroll
            for (int d = 0; d < 16; d++) w_acc += ne_s[d] * wwtp[d * O2 + tid];
            wwt_s[tid] = w_acc;
        }
        if (tid < O8) {
            float w_acc = 0.f;
#pragma unroll
            for (int d = 0; d < 16; d++) w_acc += ne_s[d] * wwsp[d * O8 + tid];
            wws_s[tid] = w_acc;
        }
    }
    __syncthreads();
    int b = tid >> 4;
    int oc = (tid & 15) * 4;
    ull acc2[2] = {0ull, 0ull};
    for (int kc = 0; kc < KC; kc++) {
        float a = xs[b * 52 + kc];
        ull a2 = pack2(a, a);
        const ull* wp2 = reinterpret_cast<const ull*>(&Wns[kc * O4 + oc]);
        fma2(acc2[0], a2, wp2[0]);
        fma2(acc2[1], a2, wp2[1]);
    }
    float acc[4];
    unpack2(acc[0], acc[1], acc2[0]);
    unpack2(acc[2], acc[3], acc2[1]);
    float* orow = out + ((size_t)b * Nn + n) * On;
#pragma unroll
    for (int j = 0; j < 4; j++) orow[oc + j] = acc[j] + bias_s[oc + j];
#pragma unroll
    for (int it = 0; it < 12; it++) {
        int o = 64 + (tid & 15) + it * 16;
        float v;
        if (o < 96) {
            int c = o - 64;
            int flat = n * O8 + c;
            int i2 = flat / Nn;
            int m = flat - i2 * Nn;
            v = fmaxf(zin[b * O8 + i2] * g_G[m] + gnnb[m], 0.f);
        } else if (o < 224) {
            v = ts_s[b] * wwt_s[o - 96];
        } else {
            v = Ms_s[b] * wws_s[o - 224];
        }
        orow[o] = v + bias_s[o];
    }
}

// ---------------- launch ----------------
extern "C" void kernel_launch(void* const* d_in, const int* in_sizes, int n_in,
                              void* d_out, int out_size) {
    const float* x    = (const float*)d_in[0];
    const float* xw   = (const float*)d_in[1];
    const float* ne   = (const float*)d_in[2];
    const int*   fa   = (const int*)d_in[3];
    const float* adj  = (const float*)d_in[4];
    const int*   stay = (const int*)d_in[5];
    const int*   jump = (const int*)d_in[6];
    const float* zin  = (const float*)d_in[7];
    const float* hodge= (const float*)d_in[8];
    const float* xew  = (const float*)d_in[9];
    const float* inc  = (const float*)d_in[10];
    const float* wp   = (const float*)d_in[11];
    const float* wwsp = (const float*)d_in[12];
    const float* wwtp = (const float*)d_in[13];
    const float* bp   = (const float*)d_in[14];
    const float* Tp   = (const float*)d_in[15];
    const float* lw   = (const float*)d_in[16];
    const float* lb   = (const float*)d_in[17];
    const float* gw   = (const float*)d_in[18];
    const float* gb   = (const float*)d_in[19];
    const int*   bidx = (const int*)d_in[20];
    float* out = (float*)d_out;

    float *pS, *pR, *pW, *pX0, *pY1, *pPP;
    float *pXEu, *pH, *pXEST, *pI;
    cudaGetSymbolAddress((void**)&pS, g_S);
    cudaGetSymbolAddress((void**)&pR, g_r);
    cudaGetSymbolAddress((void**)&pW, g_W);
    cudaGetSymbolAddress((void**)&pX0, g_X0);
    cudaGetSymbolAddress((void**)&pY1, g_Y1);
    cudaGetSymbolAddress((void**)&pPP, g_pp);
    cudaGetSymbolAddress((void**)&pXEu, g_XEu);
    cudaGetSymbolAddress((void**)&pH, g_hpart);
    cudaGetSymbolAddress((void**)&pXEST, g_XEST);
    cudaGetSymbolAddress((void**)&pI, g_ipart);

    static cudaStream_t s1 = nullptr, s2 = nullptr;
    static cudaEvent_t evRoot = nullptr, ev1 = nullptr, ev2 = nullptr;
    static bool init_done = false;
    if (!init_done) {
        cudaFuncSetAttribute(k_S_fused, cudaFuncAttributeMaxDynamicSharedMemorySize, 8 * Nn * 4);
        cudaStreamCreateWithFlags(&s1, cudaStreamNonBlocking);
        cudaStreamCreateWithFlags(&s2, cudaStreamNonBlocking);
        cudaEventCreateWithFlags(&evRoot, cudaEventDisableTiming);
        cudaEventCreateWithFlags(&ev1, cudaEventDisableTiming);
        cudaEventCreateWithFlags(&ev2, cudaEventDisableTiming);
        init_done = true;
    }

    // fork side branches off the main (capture) stream
    cudaEventRecord(evRoot, 0);
    cudaStreamWaitEvent(s1, evRoot, 0);
    cudaStreamWaitEvent(s2, evRoot, 0);

    // --- s1: supra branch (independent until epilogue) ---
    k_prep_xe2<<<(Bn * En + 255) / 256, 256, 0, s1>>>(xew, bidx, lw, lb);
    constexpr int hChunk = 512;  // mult of BK=32
    k_tfgemm<16, 128, 32, 4, 1, 4, 128, 0><<<dim3(24, 1, SPL), 128, 0, s1>>>(pXEu, hodge, pH, Bn, En, En, hChunk, nullptr);
    k_hreduce<<<dim3((En + 255) / 256, Bn), 256, 0, s1>>>(jump);
    constexpr int iChunk = 320;  // mult of BK=32 (tail guarded by k1)
    k_tfgemm<128, 16, 32, 1, 2, 2, 128, 0><<<dim3(1, 16, SPLI), 128, 0, s1>>>(inc, pXEST, pI, Nn, Bn, En, iChunk, nullptr);
    k_mreduce<<<(Bn * Nn + 255) / 256, 256, 0, s1>>>();
    cudaEventRecord(ev1, s1);

    // --- s2: misc epilogue inputs (weights outer product, temporal, ZFC rowsum) ---
    k_outer16<<<dim3(13, 16), 256, 0, s2>>>(ne, wp, pW, KC * O4);
    k_tsum<<<(Bn * Nn + 255) / 256, 256, 0, s2>>>(xw, Tp);
    k_rowsum_g<<<Nn, 256, 0, s2>>>(gw);
    cudaEventRecord(ev2, s2);

    // --- main chain: S -> diffusion GEMMs ---
    k_transpose_ne<<<(Nn * Dn + 255) / 256, 256>>>(ne);
    k_prep_x0<<<(Nn * BCp + 255) / 256, 256>>>(x);
    k_S_fused<<<Nn / 8, 256, 8 * Nn * 4>>>(ne, adj, fa, stay);
    constexpr int bigChunk = 336;  // mult of BK=16, covers 2000 over 6 planes
    k_tfgemm<128, 96, 16, 4, 4, 3, 256, 1><<<dim3(3, 16, SPL), 256>>>(pS, pX0, pPP, Nn, BCp, Nn, bigChunk, pR);
    k_reduceY<<<(Nn * BCp + 255) / 256, 256>>>(pY1);
    k_tfgemm<128, 96, 16, 4, 4, 3, 256, 1><<<dim3(3, 16, SPL), 256>>>(pS, pY1, pPP, Nn, BCp, Nn, bigChunk, pR);

    // join side branches, then fused epilogue (sums Y2 partials in-block)
    cudaStreamWaitEvent(0, ev1, 0);
    cudaStreamWaitEvent(0, ev2, 0);
    k_epilogue<<<Nn, 256>>>(x, zin, gb, ne, bp, wwtp, wwsp, out);
}